// round 16
// baseline (speedup 1.0000x reference)
#include <cuda_runtime.h>
#include <cuda_bf16.h>
#include <mma.h>
#include <cstdint>

using namespace nvcuda;

#define BDIM 64
#define TDIM 2048
#define DDIM 256
#define HDIM 256
#define G3   768
#define MTOT (BDIM * TDIM)

__device__ float g_xg[(size_t)MTOT * G3];
__device__ __nv_bfloat16 g_xh[(size_t)MTOT * DDIM];
__device__ __nv_bfloat16 g_xl[(size_t)MTOT * DDIM];
__device__ __nv_bfloat16 g_wh[(size_t)G3 * DDIM];
__device__ __nv_bfloat16 g_wl[(size_t)G3 * DDIM];

// ---------------- f32x2 helpers ----------------
__device__ __forceinline__ unsigned long long pk2(float x, float y) {
    unsigned long long r;
    asm("mov.b64 %0, {%1, %2};" : "=l"(r) : "f"(x), "f"(y));
    return r;
}
__device__ __forceinline__ void upk2(unsigned long long p, float& x, float& y) {
    asm("mov.b64 {%0, %1}, %2;" : "=f"(x), "=f"(y) : "l"(p));
}
__device__ __forceinline__ unsigned long long fma2(unsigned long long a,
                                                   unsigned long long b,
                                                   unsigned long long c) {
    unsigned long long d;
    asm("fma.rn.f32x2 %0, %1, %2, %3;" : "=l"(d) : "l"(a), "l"(b), "l"(c));
    return d;
}

// ---------------- Kernel 0: fp32 -> bf16 hi/lo split ----------------
__global__ __launch_bounds__(256) void split_bf16(const float4* __restrict__ src,
                                                  __nv_bfloat162* __restrict__ dh,
                                                  __nv_bfloat162* __restrict__ dl,
                                                  int n4) {
    int i = blockIdx.x * 256 + threadIdx.x;
    if (i >= n4) return;
    float4 v = src[i];
    __nv_bfloat16 h0 = __float2bfloat16(v.x), h1 = __float2bfloat16(v.y);
    __nv_bfloat16 h2 = __float2bfloat16(v.z), h3 = __float2bfloat16(v.w);
    __nv_bfloat16 l0 = __float2bfloat16(v.x - __bfloat162float(h0));
    __nv_bfloat16 l1 = __float2bfloat16(v.y - __bfloat162float(h1));
    __nv_bfloat16 l2 = __float2bfloat16(v.z - __bfloat162float(h2));
    __nv_bfloat16 l3 = __float2bfloat16(v.w - __bfloat162float(h3));
    __nv_bfloat162 a; a.x = h0; a.y = h1;
    __nv_bfloat162 b; b.x = h2; b.y = h3;
    dh[2 * i] = a; dh[2 * i + 1] = b;
    a.x = l0; a.y = l1; b.x = l2; b.y = l3;
    dl[2 * i] = a; dl[2 * i + 1] = b;
}

// ---------------- Kernel 1: wmma bf16 split-GEMM projection ----------------
// D[M=131072, N=768] = Ah*Bh^T + Ah*Bl^T + Al*Bh^T + bias
// tile 64x64, BK=32, 256 threads (8 warps as 2m x 4n)
#define PBM 64
#define PBN 64
#define PBK 32
#define AS  40    // A smem row stride (bf16), mult of 8
#define BS  40    // B smem row stride
#define CS  68    // C smem row stride (float), mult of 4

__global__ __launch_bounds__(256) void proj_wmma(const float* __restrict__ bias) {
    __shared__ __nv_bfloat16 As_h[PBM * AS], As_l[PBM * AS];
    __shared__ __nv_bfloat16 Bs_h[PBN * BS], Bs_l[PBN * BS];
    __shared__ float Cs[PBM * CS];

    const int tid = threadIdx.x, wid = tid >> 5;
    const int gn = blockIdx.x * PBN;    // n fast: 12 CTAs share A rows via L2
    const int gm = blockIdx.y * PBM;
    const int wm = wid & 1, wn = wid >> 1;

    // loader: each thread 1 uint4 (8 bf16) per matrix per tile
    const int lrow = tid >> 2, lk8 = (tid & 3) * 8;

    wmma::fragment<wmma::accumulator, 16, 16, 16, float> c0, c1;
    wmma::fill_fragment(c0, 0.f);
    wmma::fill_fragment(c1, 0.f);

    for (int kt = 0; kt < DDIM / PBK; kt++) {
        const int ko = kt * PBK + lk8;
        *(uint4*)&As_h[lrow * AS + lk8] = *(const uint4*)(g_xh + (size_t)(gm + lrow) * DDIM + ko);
        *(uint4*)&As_l[lrow * AS + lk8] = *(const uint4*)(g_xl + (size_t)(gm + lrow) * DDIM + ko);
        *(uint4*)&Bs_h[lrow * BS + lk8] = *(const uint4*)(g_wh + (size_t)(gn + lrow) * DDIM + ko);
        *(uint4*)&Bs_l[lrow * BS + lk8] = *(const uint4*)(g_wl + (size_t)(gn + lrow) * DDIM + ko);
        __syncthreads();

#pragma unroll
        for (int kk = 0; kk < PBK; kk += 16) {
            wmma::fragment<wmma::matrix_a, 16, 16, 16, __nv_bfloat16, wmma::row_major> ah0, ah1, al0, al1;
            wmma::fragment<wmma::matrix_b, 16, 16, 16, __nv_bfloat16, wmma::col_major> bh, bl;
            wmma::load_matrix_sync(ah0, &As_h[(wm * 32 + 0)  * AS + kk], AS);
            wmma::load_matrix_sync(ah1, &As_h[(wm * 32 + 16) * AS + kk], AS);
            wmma::load_matrix_sync(al0, &As_l[(wm * 32 + 0)  * AS + kk], AS);
            wmma::load_matrix_sync(al1, &As_l[(wm * 32 + 16) * AS + kk], AS);
            wmma::load_matrix_sync(bh, &Bs_h[(wn * 16) * BS + kk], BS);
            wmma::load_matrix_sync(bl, &Bs_l[(wn * 16) * BS + kk], BS);
            wmma::mma_sync(c0, ah0, bh, c0);
            wmma::mma_sync(c1, ah1, bh, c1);
            wmma::mma_sync(c0, ah0, bl, c0);
            wmma::mma_sync(c1, ah1, bl, c1);
            wmma::mma_sync(c0, al0, bh, c0);
            wmma::mma_sync(c1, al1, bh, c1);
        }
        __syncthreads();
    }

    // epilogue: frags -> smem -> (+bias) -> gmem
    wmma::store_matrix_sync(&Cs[(wm * 32 + 0)  * CS + wn * 16], c0, CS, wmma::mem_row_major);
    wmma::store_matrix_sync(&Cs[(wm * 32 + 16) * CS + wn * 16], c1, CS, wmma::mem_row_major);
    __syncthreads();

    const int erow = tid >> 2, ec16 = (tid & 3) * 16;
#pragma unroll
    for (int j = 0; j < 16; j += 4) {
        float4 bb = *(const float4*)&bias[gn + ec16 + j];
        float4 v = *(const float4*)&Cs[erow * CS + ec16 + j];
        v.x += bb.x; v.y += bb.y; v.z += bb.z; v.w += bb.w;
        *(float4*)&g_xg[(size_t)(gm + erow) * G3 + gn + ec16 + j] = v;
    }
}

// ---------------- Kernel 2: CLSZ=4, register W, cluster barrier (R7/R11, verbatim) ----------------
#define CLSZ 4
#define RTH  384
#define IDXC 64
#define NROW 192

__device__ __forceinline__ float sigm_f(float x) { return 1.f / (1.f + __expf(-x)); }
__device__ __forceinline__ float tanh_f(float x) { return 1.f - 2.f / (__expf(2.f * x) + 1.f); }

__device__ __forceinline__ void st_dsmem_u64(uint32_t saddr, uint32_t rk, unsigned long long v) {
    uint32_t ra;
    asm volatile("mapa.shared::cluster.u32 %0, %1, %2;" : "=r"(ra) : "r"(saddr), "r"(rk));
    asm volatile("st.shared::cluster.u64 [%0], %1;" :: "r"(ra), "l"(v) : "memory");
}
__device__ __forceinline__ void cluster_arrive() {
    asm volatile("barrier.cluster.arrive.aligned;" ::: "memory");
}
__device__ __forceinline__ void cluster_wait() {
    asm volatile("barrier.cluster.wait.aligned;" ::: "memory");
}

__global__ __launch_bounds__(RTH, 1) void gru_rec(const float* __restrict__ h0,
                                                  const float* __restrict__ W_hh,
                                                  const float* __restrict__ b_hh,
                                                  float* __restrict__ hs,
                                                  float* __restrict__ hT) {
    __shared__ alignas(16) float sh_h[2][2 * HDIM];
    __shared__ alignas(16) float2 sh_hgA[NROW];
    __shared__ alignas(16) float2 sh_hgB[NROW];

    uint32_t rank; asm("mov.u32 %0, %%cluster_ctarank;" : "=r"(rank));
    const int tid = threadIdx.x;
    const int cb = (blockIdx.x >> 2) * 2;

    const int kh = tid >= NROW;
    const int r  = tid - kh * NROW;
    const int g  = r >> 6, il = r & 63;
    const int grow = g * HDIM + (int)rank * IDXC + il;

    unsigned long long wq[64];
    {
        const ulonglong2* wp = (const ulonglong2*)(W_hh + (size_t)grow * HDIM + kh * 128);
#pragma unroll
        for (int j = 0; j < 32; j++) { ulonglong2 u = wp[j]; wq[2*j] = u.x; wq[2*j+1] = u.y; }
    }
    float bhr = 0.f, bhz = 0.f, bhn = 0.f;
    if (tid < 128) {
        int gil = tid & 63, gi = (int)rank * IDXC + gil;
        bhr = b_hh[gi]; bhz = b_hh[HDIM + gi]; bhn = b_hh[2 * HDIM + gi];
    }
    for (int i = tid; i < 2 * HDIM; i += RTH) {
        int b = i >> 8, k = i & 255;
        sh_h[0][b * HDIM + k] = h0[(size_t)(cb + b) * HDIM + k];
    }
    __syncthreads();
    cluster_arrive();
    cluster_wait();

    const int gb = tid >> 6, ggil = tid & 63;
    const size_t xg_gate_base = ((size_t)(cb + gb) * TDIM) * G3
                              + (size_t)rank * IDXC + ggil;

    const uint32_t h_s = (uint32_t)__cvta_generic_to_shared(sh_h);

    for (int t = 0; t < TDIM; t++) {
        const int cur = t & 1;
        const float* hb = sh_h[cur];

        float xr = 0.f, xz = 0.f, xn = 0.f;
        if (tid < 128) {
            const float* xp = g_xg + xg_gate_base + (size_t)t * G3;
            xr = xp[0]; xz = xp[256]; xn = xp[512];
        }

        const ulonglong2* hpA = (const ulonglong2*)(hb + kh * 128);
        const ulonglong2* hpB = (const ulonglong2*)(hb + HDIM + kh * 128);
        unsigned long long a0a = 0ull, a0b = 0ull, a1a = 0ull, a1b = 0ull;
#pragma unroll
        for (int c = 0; c < 16; c++) {
            ulonglong2 vA = hpA[c];
            a0a = fma2(wq[2*c+0], vA.x, a0a); a0a = fma2(wq[2*c+1], vA.y, a0a);
            ulonglong2 vB = hpB[c];
            a1a = fma2(wq[2*c+0], vB.x, a1a); a1a = fma2(wq[2*c+1], vB.y, a1a);
            ulonglong2 vA2 = hpA[16 + c];
            a0b = fma2(wq[32+2*c+0], vA2.x, a0b); a0b = fma2(wq[32+2*c+1], vA2.y, a0b);
            ulonglong2 vB2 = hpB[16 + c];
            a1b = fma2(wq[32+2*c+0], vB2.x, a1b); a1b = fma2(wq[32+2*c+1], vB2.y, a1b);
        }
        float s0, s1, xl, xh2;
        unsigned long long t0 = fma2(pk2(1.f, 1.f), a0a, a0b);
        upk2(t0, xl, xh2); s0 = xl + xh2;
        unsigned long long t1 = fma2(pk2(1.f, 1.f), a1a, a1b);
        upk2(t1, xl, xh2); s1 = xl + xh2;
        if (kh) sh_hgB[r] = make_float2(s0, s1);
        else    sh_hgA[r] = make_float2(s0, s1);
        __syncthreads();

        float hnew = 0.f, hpart = 0.f;
        int b = gb, gi = (int)rank * IDXC + ggil;
        if (tid < 128) {
            const int gil = ggil;
            float2 rA = sh_hgA[gil],        rB = sh_hgB[gil];
            float2 zA = sh_hgA[64 + gil],   zB = sh_hgB[64 + gil];
            float2 nA = sh_hgA[128 + gil],  nB = sh_hgB[128 + gil];
            float hr  = b ? (rA.y + rB.y) : (rA.x + rB.x);
            float hz  = b ? (zA.y + zB.y) : (zA.x + zB.x);
            float hnv = b ? (nA.y + nB.y) : (nA.x + nB.x);
            float hprev = hb[b * HDIM + gi];
            float rg = sigm_f(xr + hr + bhr);
            float zg = sigm_f(xz + hz + bhz);
            float ng = tanh_f(xn + rg * (hnv + bhn));
            hnew = (1.f - zg) * ng + zg * hprev;

            hpart = __shfl_down_sync(0xffffffffu, hnew, 1);
            if (t < TDIM - 1 && (ggil & 1) == 0) {
                unsigned long long pv = pk2(hnew, hpart);
                uint32_t laddr = h_s + 4u * (uint32_t)((cur ^ 1) * (2 * HDIM) + b * HDIM + gi);
#pragma unroll
                for (uint32_t dr = 0; dr < CLSZ; dr++) st_dsmem_u64(laddr, dr, pv);
            }
        }
        cluster_arrive();
        if (tid < 128) {
            if ((ggil & 1) == 0)
                *(float2*)&hs[((size_t)(cb + b) * TDIM + t) * HDIM + gi] = make_float2(hnew, hpart);
            if (t == TDIM - 1) hT[(size_t)(cb + b) * HDIM + gi] = hnew;
        }
        cluster_wait();
    }
}

// ---------------- launch ----------------
extern "C" void kernel_launch(void* const* d_in, const int* in_sizes, int n_in,
                              void* d_out, int out_size) {
    (void)in_sizes; (void)n_in; (void)out_size;
    const float* x    = (const float*)d_in[0];
    const float* h0   = (const float*)d_in[1];
    const float* W_ih = (const float*)d_in[2];
    const float* W_hh = (const float*)d_in[3];
    const float* b_ih = (const float*)d_in[4];
    const float* b_hh = (const float*)d_in[5];
    float* out = (float*)d_out;
    float* hs = out;
    float* hT = out + (size_t)MTOT * HDIM;

    void *p_xh, *p_xl, *p_wh, *p_wl;
    cudaGetSymbolAddress(&p_xh, g_xh);
    cudaGetSymbolAddress(&p_xl, g_xl);
    cudaGetSymbolAddress(&p_wh, g_wh);
    cudaGetSymbolAddress(&p_wl, g_wl);

    // split x and W_ih into bf16 hi/lo
    {
        int n4x = (MTOT * DDIM) / 4;
        split_bf16<<<(n4x + 255) / 256, 256>>>((const float4*)x,
                                               (__nv_bfloat162*)p_xh, (__nv_bfloat162*)p_xl, n4x);
        int n4w = (G3 * DDIM) / 4;
        split_bf16<<<(n4w + 255) / 256, 256>>>((const float4*)W_ih,
                                               (__nv_bfloat162*)p_wh, (__nv_bfloat162*)p_wl, n4w);
    }

    // tensor-core projection (wmma bf16, 3-pass split)
    dim3 gp(G3 / PBN, MTOT / PBM);
    proj_wmma<<<gp, 256>>>(b_ih);

    // recurrence
    cudaLaunchConfig_t cfg = {};
    cfg.gridDim = dim3(32 * CLSZ, 1, 1);
    cfg.blockDim = dim3(RTH, 1, 1);
    cfg.dynamicSmemBytes = 0;
    cfg.stream = 0;
    cudaLaunchAttribute attrs[1];
    attrs[0].id = cudaLaunchAttributeClusterDimension;
    attrs[0].val.clusterDim.x = CLSZ;
    attrs[0].val.clusterDim.y = 1;
    attrs[0].val.clusterDim.z = 1;
    cfg.attrs = attrs;
    cfg.numAttrs = 1;
    cudaLaunchKernelEx(&cfg, gru_rec, h0, W_hh, b_hh, hs, hT);
}

// round 17
// speedup vs baseline: 1.0492x; 1.0492x over previous
#include <cuda_runtime.h>
#include <cuda_bf16.h>
#include <mma.h>
#include <cstdint>

using namespace nvcuda;

#define BDIM 64
#define TDIM 2048
#define DDIM 256
#define HDIM 256
#define G3   768
#define MTOT (BDIM * TDIM)

__device__ float g_xg[(size_t)MTOT * G3];
__device__ __nv_bfloat16 g_wh[(size_t)G3 * DDIM];
__device__ __nv_bfloat16 g_wl[(size_t)G3 * DDIM];

// ---------------- f32x2 helpers ----------------
__device__ __forceinline__ unsigned long long pk2(float x, float y) {
    unsigned long long r;
    asm("mov.b64 %0, {%1, %2};" : "=l"(r) : "f"(x), "f"(y));
    return r;
}
__device__ __forceinline__ void upk2(unsigned long long p, float& x, float& y) {
    asm("mov.b64 {%0, %1}, %2;" : "=f"(x), "=f"(y) : "l"(p));
}
__device__ __forceinline__ unsigned long long fma2(unsigned long long a,
                                                   unsigned long long b,
                                                   unsigned long long c) {
    unsigned long long d;
    asm("fma.rn.f32x2 %0, %1, %2, %3;" : "=l"(d) : "l"(a), "l"(b), "l"(c));
    return d;
}

// ---------------- Kernel 0: fp32 -> bf16 hi/lo split (W only) ----------------
__global__ __launch_bounds__(256) void split_bf16(const float4* __restrict__ src,
                                                  __nv_bfloat162* __restrict__ dh,
                                                  __nv_bfloat162* __restrict__ dl,
                                                  int n4) {
    int i = blockIdx.x * 256 + threadIdx.x;
    if (i >= n4) return;
    float4 v = src[i];
    __nv_bfloat16 h0 = __float2bfloat16(v.x), h1 = __float2bfloat16(v.y);
    __nv_bfloat16 h2 = __float2bfloat16(v.z), h3 = __float2bfloat16(v.w);
    __nv_bfloat16 l0 = __float2bfloat16(v.x - __bfloat162float(h0));
    __nv_bfloat16 l1 = __float2bfloat16(v.y - __bfloat162float(h1));
    __nv_bfloat16 l2 = __float2bfloat16(v.z - __bfloat162float(h2));
    __nv_bfloat16 l3 = __float2bfloat16(v.w - __bfloat162float(h3));
    __nv_bfloat162 a; a.x = h0; a.y = h1;
    __nv_bfloat162 b; b.x = h2; b.y = h3;
    dh[2 * i] = a; dh[2 * i + 1] = b;
    a.x = l0; a.y = l1; b.x = l2; b.y = l3;
    dl[2 * i] = a; dl[2 * i + 1] = b;
}

// ---------------- Kernel 1: pipelined wmma split-GEMM projection ----------------
// D[M, 768] = Ah*Bh^T + Ah*Bl^T + Al*Bh^T + bias; A converted fp32->hi/lo in-kernel.
// tile 128x64, BK=32, 2-stage smem double buffer, 256 thr (8 warps = 4m x 2n)
#define PBM 128
#define PBN 64
#define PBK 32
#define ASTR 40
#define BSTR 40
#define AH_OFF 0
#define AL_OFF 10240
#define BH_OFF 20480
#define BL_OFF 25600
#define STAGE  30720
#define SMTOT  (2 * STAGE)
#define CSTR 68

__device__ __forceinline__ void f4_to_bf(float4 v, uint2& h, uint2& l) {
    __nv_bfloat162 h0 = __floats2bfloat162_rn(v.x, v.y);
    __nv_bfloat162 h1 = __floats2bfloat162_rn(v.z, v.w);
    __nv_bfloat162 l0 = __floats2bfloat162_rn(v.x - __bfloat162float(h0.x),
                                              v.y - __bfloat162float(h0.y));
    __nv_bfloat162 l1 = __floats2bfloat162_rn(v.z - __bfloat162float(h1.x),
                                              v.w - __bfloat162float(h1.y));
    h.x = *(uint32_t*)&h0; h.y = *(uint32_t*)&h1;
    l.x = *(uint32_t*)&l0; l.y = *(uint32_t*)&l1;
}

__global__ __launch_bounds__(256) void proj_tc(const float* __restrict__ x,
                                               const float* __restrict__ bias) {
    extern __shared__ char sm[];
    const int tid = threadIdx.x, wid = tid >> 5;
    const int gn = blockIdx.x * PBN;     // n fast: 12 CTAs share A rows via L2
    const int gm = blockIdx.y * PBM;
    const int wm = wid & 3, wn = wid >> 2;

    // loader mapping
    const int arow = tid >> 1, ahalf = tid & 1;   // A: 128 rows x 2 halves of 16 cols
    const int brow = tid >> 2, bch = tid & 3;     // B: 64 rows x 4 chunks of 8 cols
    const float* aptr = x + (size_t)(gm + arow) * DDIM + ahalf * 16;
    const __nv_bfloat16* bhp = g_wh + (size_t)(gn + brow) * DDIM + bch * 8;
    const __nv_bfloat16* blp = g_wl + (size_t)(gn + brow) * DDIM + bch * 8;
    const uint32_t a_soff = (uint32_t)(arow * ASTR + ahalf * 16) * 2u;
    const uint32_t b_soff = (uint32_t)(brow * BSTR + bch * 8) * 2u;

    wmma::fragment<wmma::accumulator, 16, 16, 16, float> c[2][2];
#pragma unroll
    for (int i = 0; i < 2; i++)
#pragma unroll
        for (int j = 0; j < 2; j++) wmma::fill_fragment(c[i][j], 0.f);

    float4 va[4]; uint4 vbh, vbl;
    // prologue: tile 0
#pragma unroll
    for (int j = 0; j < 4; j++) va[j] = *(const float4*)(aptr + j * 4);
    vbh = *(const uint4*)bhp;
    vbl = *(const uint4*)blp;
    {
        char* base = sm;
#pragma unroll
        for (int j = 0; j < 4; j++) {
            uint2 h, l; f4_to_bf(va[j], h, l);
            *(uint2*)(base + AH_OFF + a_soff + j * 8) = h;
            *(uint2*)(base + AL_OFF + a_soff + j * 8) = l;
        }
        *(uint4*)(base + BH_OFF + b_soff) = vbh;
        *(uint4*)(base + BL_OFF + b_soff) = vbl;
    }
    __syncthreads();

    for (int kt = 0; kt < DDIM / PBK; kt++) {
        if (kt < DDIM / PBK - 1) {
            const int ko = (kt + 1) * PBK;
#pragma unroll
            for (int j = 0; j < 4; j++) va[j] = *(const float4*)(aptr + ko + j * 4);
            vbh = *(const uint4*)(bhp + ko);
            vbl = *(const uint4*)(blp + ko);
        }
        // mma on stage kt&1
        {
            const char* base = sm + (kt & 1) * STAGE;
            const __nv_bfloat16* Ah = (const __nv_bfloat16*)(base + AH_OFF);
            const __nv_bfloat16* Al = (const __nv_bfloat16*)(base + AL_OFF);
            const __nv_bfloat16* Bh = (const __nv_bfloat16*)(base + BH_OFF);
            const __nv_bfloat16* Bl = (const __nv_bfloat16*)(base + BL_OFF);
#pragma unroll
            for (int kk = 0; kk < PBK; kk += 16) {
                wmma::fragment<wmma::matrix_a, 16, 16, 16, __nv_bfloat16, wmma::row_major> ah[2], al[2];
                wmma::fragment<wmma::matrix_b, 16, 16, 16, __nv_bfloat16, wmma::col_major> bh[2], bl[2];
#pragma unroll
                for (int f = 0; f < 2; f++) {
                    wmma::load_matrix_sync(ah[f], Ah + (wm * 32 + f * 16) * ASTR + kk, ASTR);
                    wmma::load_matrix_sync(al[f], Al + (wm * 32 + f * 16) * ASTR + kk, ASTR);
                    wmma::load_matrix_sync(bh[f], Bh + (wn * 32 + f * 16) * BSTR + kk, BSTR);
                    wmma::load_matrix_sync(bl[f], Bl + (wn * 32 + f * 16) * BSTR + kk, BSTR);
                }
#pragma unroll
                for (int fm = 0; fm < 2; fm++)
#pragma unroll
                    for (int fn = 0; fn < 2; fn++) {
                        wmma::mma_sync(c[fm][fn], ah[fm], bh[fn], c[fm][fn]);
                        wmma::mma_sync(c[fm][fn], ah[fm], bl[fn], c[fm][fn]);
                        wmma::mma_sync(c[fm][fn], al[fm], bh[fn], c[fm][fn]);
                    }
            }
        }
        if (kt < DDIM / PBK - 1) {
            char* base = sm + ((kt + 1) & 1) * STAGE;
#pragma unroll
            for (int j = 0; j < 4; j++) {
                uint2 h, l; f4_to_bf(va[j], h, l);
                *(uint2*)(base + AH_OFF + a_soff + j * 8) = h;
                *(uint2*)(base + AL_OFF + a_soff + j * 8) = l;
            }
            *(uint4*)(base + BH_OFF + b_soff) = vbh;
            *(uint4*)(base + BL_OFF + b_soff) = vbl;
        }
        __syncthreads();
    }

    // epilogue: frags -> smem (alias stages) -> +bias -> gmem
    float* Cs = (float*)sm;
#pragma unroll
    for (int fm = 0; fm < 2; fm++)
#pragma unroll
        for (int fn = 0; fn < 2; fn++)
            wmma::store_matrix_sync(&Cs[(wm * 32 + fm * 16) * CSTR + wn * 32 + fn * 16],
                                    c[fm][fn], CSTR, wmma::mem_row_major);
    __syncthreads();

    const int erow = tid >> 1, ehalf = tid & 1;
#pragma unroll
    for (int j = 0; j < 8; j++) {
        int col = ehalf * 32 + j * 4;
        float4 bb = *(const float4*)&bias[gn + col];
        float4 v = *(const float4*)&Cs[erow * CSTR + col];
        v.x += bb.x; v.y += bb.y; v.z += bb.z; v.w += bb.w;
        *(float4*)&g_xg[(size_t)(gm + erow) * G3 + gn + col] = v;
    }
}

// ---------------- Kernel 2: CLSZ=4, register W, cluster barrier (R7/R11, verbatim) ----------------
#define CLSZ 4
#define RTH  384
#define IDXC 64
#define NROW 192

__device__ __forceinline__ float sigm_f(float x) { return 1.f / (1.f + __expf(-x)); }
__device__ __forceinline__ float tanh_f(float x) { return 1.f - 2.f / (__expf(2.f * x) + 1.f); }

__device__ __forceinline__ void st_dsmem_u64(uint32_t saddr, uint32_t rk, unsigned long long v) {
    uint32_t ra;
    asm volatile("mapa.shared::cluster.u32 %0, %1, %2;" : "=r"(ra) : "r"(saddr), "r"(rk));
    asm volatile("st.shared::cluster.u64 [%0], %1;" :: "r"(ra), "l"(v) : "memory");
}
__device__ __forceinline__ void cluster_arrive() {
    asm volatile("barrier.cluster.arrive.aligned;" ::: "memory");
}
__device__ __forceinline__ void cluster_wait() {
    asm volatile("barrier.cluster.wait.aligned;" ::: "memory");
}

__global__ __launch_bounds__(RTH, 1) void gru_rec(const float* __restrict__ h0,
                                                  const float* __restrict__ W_hh,
                                                  const float* __restrict__ b_hh,
                                                  float* __restrict__ hs,
                                                  float* __restrict__ hT) {
    __shared__ alignas(16) float sh_h[2][2 * HDIM];
    __shared__ alignas(16) float2 sh_hgA[NROW];
    __shared__ alignas(16) float2 sh_hgB[NROW];

    uint32_t rank; asm("mov.u32 %0, %%cluster_ctarank;" : "=r"(rank));
    const int tid = threadIdx.x;
    const int cb = (blockIdx.x >> 2) * 2;

    const int kh = tid >= NROW;
    const int r  = tid - kh * NROW;
    const int g  = r >> 6, il = r & 63;
    const int grow = g * HDIM + (int)rank * IDXC + il;

    unsigned long long wq[64];
    {
        const ulonglong2* wp = (const ulonglong2*)(W_hh + (size_t)grow * HDIM + kh * 128);
#pragma unroll
        for (int j = 0; j < 32; j++) { ulonglong2 u = wp[j]; wq[2*j] = u.x; wq[2*j+1] = u.y; }
    }
    float bhr = 0.f, bhz = 0.f, bhn = 0.f;
    if (tid < 128) {
        int gil = tid & 63, gi = (int)rank * IDXC + gil;
        bhr = b_hh[gi]; bhz = b_hh[HDIM + gi]; bhn = b_hh[2 * HDIM + gi];
    }
    for (int i = tid; i < 2 * HDIM; i += RTH) {
        int b = i >> 8, k = i & 255;
        sh_h[0][b * HDIM + k] = h0[(size_t)(cb + b) * HDIM + k];
    }
    __syncthreads();
    cluster_arrive();
    cluster_wait();

    const int gb = tid >> 6, ggil = tid & 63;
    const size_t xg_gate_base = ((size_t)(cb + gb) * TDIM) * G3
                              + (size_t)rank * IDXC + ggil;

    const uint32_t h_s = (uint32_t)__cvta_generic_to_shared(sh_h);

    for (int t = 0; t < TDIM; t++) {
        const int cur = t & 1;
        const float* hb = sh_h[cur];

        float xr = 0.f, xz = 0.f, xn = 0.f;
        if (tid < 128) {
            const float* xp = g_xg + xg_gate_base + (size_t)t * G3;
            xr = xp[0]; xz = xp[256]; xn = xp[512];
        }

        const ulonglong2* hpA = (const ulonglong2*)(hb + kh * 128);
        const ulonglong2* hpB = (const ulonglong2*)(hb + HDIM + kh * 128);
        unsigned long long a0a = 0ull, a0b = 0ull, a1a = 0ull, a1b = 0ull;
#pragma unroll
        for (int c = 0; c < 16; c++) {
            ulonglong2 vA = hpA[c];
            a0a = fma2(wq[2*c+0], vA.x, a0a); a0a = fma2(wq[2*c+1], vA.y, a0a);
            ulonglong2 vB = hpB[c];
            a1a = fma2(wq[2*c+0], vB.x, a1a); a1a = fma2(wq[2*c+1], vB.y, a1a);
            ulonglong2 vA2 = hpA[16 + c];
            a0b = fma2(wq[32+2*c+0], vA2.x, a0b); a0b = fma2(wq[32+2*c+1], vA2.y, a0b);
            ulonglong2 vB2 = hpB[16 + c];
            a1b = fma2(wq[32+2*c+0], vB2.x, a1b); a1b = fma2(wq[32+2*c+1], vB2.y, a1b);
        }
        float s0, s1, xl, xh2;
        unsigned long long t0 = fma2(pk2(1.f, 1.f), a0a, a0b);
        upk2(t0, xl, xh2); s0 = xl + xh2;
        unsigned long long t1 = fma2(pk2(1.f, 1.f), a1a, a1b);
        upk2(t1, xl, xh2); s1 = xl + xh2;
        if (kh) sh_hgB[r] = make_float2(s0, s1);
        else    sh_hgA[r] = make_float2(s0, s1);
        __syncthreads();

        float hnew = 0.f, hpart = 0.f;
        int b = gb, gi = (int)rank * IDXC + ggil;
        if (tid < 128) {
            const int gil = ggil;
            float2 rA = sh_hgA[gil],        rB = sh_hgB[gil];
            float2 zA = sh_hgA[64 + gil],   zB = sh_hgB[64 + gil];
            float2 nA = sh_hgA[128 + gil],  nB = sh_hgB[128 + gil];
            float hr  = b ? (rA.y + rB.y) : (rA.x + rB.x);
            float hz  = b ? (zA.y + zB.y) : (zA.x + zB.x);
            float hnv = b ? (nA.y + nB.y) : (nA.x + nB.x);
            float hprev = hb[b * HDIM + gi];
            float rg = sigm_f(xr + hr + bhr);
            float zg = sigm_f(xz + hz + bhz);
            float ng = tanh_f(xn + rg * (hnv + bhn));
            hnew = (1.f - zg) * ng + zg * hprev;

            hpart = __shfl_down_sync(0xffffffffu, hnew, 1);
            if (t < TDIM - 1 && (ggil & 1) == 0) {
                unsigned long long pv = pk2(hnew, hpart);
                uint32_t laddr = h_s + 4u * (uint32_t)((cur ^ 1) * (2 * HDIM) + b * HDIM + gi);
#pragma unroll
                for (uint32_t dr = 0; dr < CLSZ; dr++) st_dsmem_u64(laddr, dr, pv);
            }
        }
        cluster_arrive();
        if (tid < 128) {
            if ((ggil & 1) == 0)
                *(float2*)&hs[((size_t)(cb + b) * TDIM + t) * HDIM + gi] = make_float2(hnew, hpart);
            if (t == TDIM - 1) hT[(size_t)(cb + b) * HDIM + gi] = hnew;
        }
        cluster_wait();
    }
}

// ---------------- launch ----------------
extern "C" void kernel_launch(void* const* d_in, const int* in_sizes, int n_in,
                              void* d_out, int out_size) {
    (void)in_sizes; (void)n_in; (void)out_size;
    const float* x    = (const float*)d_in[0];
    const float* h0   = (const float*)d_in[1];
    const float* W_ih = (const float*)d_in[2];
    const float* W_hh = (const float*)d_in[3];
    const float* b_ih = (const float*)d_in[4];
    const float* b_hh = (const float*)d_in[5];
    float* out = (float*)d_out;
    float* hs = out;
    float* hT = out + (size_t)MTOT * HDIM;

    void *p_wh, *p_wl;
    cudaGetSymbolAddress(&p_wh, g_wh);
    cudaGetSymbolAddress(&p_wl, g_wl);

    // split W_ih into bf16 hi/lo (tiny)
    {
        int n4w = (G3 * DDIM) / 4;
        split_bf16<<<(n4w + 255) / 256, 256>>>((const float4*)W_ih,
                                               (__nv_bfloat162*)p_wh, (__nv_bfloat162*)p_wl, n4w);
    }

    // pipelined tensor-core projection (A converted in-kernel)
    cudaFuncSetAttribute(proj_tc, cudaFuncAttributeMaxDynamicSharedMemorySize, SMTOT);
    dim3 gp(G3 / PBN, MTOT / PBM);
    proj_tc<<<gp, 256, SMTOT>>>(x, b_ih);

    // recurrence
    cudaLaunchConfig_t cfg = {};
    cfg.gridDim = dim3(32 * CLSZ, 1, 1);
    cfg.blockDim = dim3(RTH, 1, 1);
    cfg.dynamicSmemBytes = 0;
    cfg.stream = 0;
    cudaLaunchAttribute attrs[1];
    attrs[0].id = cudaLaunchAttributeClusterDimension;
    attrs[0].val.clusterDim.x = CLSZ;
    attrs[0].val.clusterDim.y = 1;
    attrs[0].val.clusterDim.z = 1;
    cfg.attrs = attrs;
    cfg.numAttrs = 1;
    cudaLaunchKernelEx(&cfg, gru_rec, h0, W_hh, b_hh, hs, hT);
}